// round 11
// baseline (speedup 1.0000x reference)
#include <cuda_runtime.h>
#include <cuda_fp16.h>
#include <cstdint>

__device__ float g_doff[2 * 144 * 256 * 256];
__device__ float g_aligned[2 * 64 * 256 * 256];
__device__ float g_x1[2 * 64 * 256 * 256];

static constexpr int Hc = 256, Wc = 256, HWc = Hc * Wc;

// smem (uint32 words):
//  Bst: 8 channel-PAIRS x 3 rows x 264 (fp16x2: lo=ch even, hi=ch odd)
//  Ah:  64 m x 84 (72 k-pairs in tap-major order: idx = tap*8 + pair)
static constexpr int BSTR = 264;
static constexpr int BST_U = 8 * 3 * BSTR;    // 6336
static constexpr int ASTR = 84;
static constexpr int AST_U = 64 * ASTR;       // 5376
static constexpr int SMEM_U = BST_U + AST_U;  // 11712
static constexpr size_t SMEM_BYTES = (size_t)SMEM_U * 4;

__device__ __forceinline__ uint32_t packh2(float lo, float hi) {
  __half2 h = __floats2half2_rn(lo, hi);  // .x = lo half
  return *reinterpret_cast<uint32_t*>(&h);
}
__device__ __forceinline__ void mma16(float* c, uint32_t a0, uint32_t a1,
                                      uint32_t a2, uint32_t a3, uint32_t b0,
                                      uint32_t b1) {
  asm volatile(
      "mma.sync.aligned.m16n8k16.row.col.f32.f16.f16.f32 "
      "{%0,%1,%2,%3}, {%4,%5,%6,%7}, {%8,%9}, {%0,%1,%2,%3};"
      : "+f"(c[0]), "+f"(c[1]), "+f"(c[2]), "+f"(c[3])
      : "r"(a0), "r"(a1), "r"(a2), "r"(a3), "r"(b0), "r"(b1));
}

// CTA: one full image row y (256 px) x 64 output channels.
// 8 warps: warp tile 32m x 64n. K chunked by 144 (16 ic x 9 taps, tap-major).
// Single-fp16 A and B (10-bit mantissa each; error adds in quadrature).
template <int NHALF>  // IC = NHALF*64
__global__ void __launch_bounds__(256, 2)
conv3x3_mma(const float* __restrict__ inA, const float* __restrict__ inB,
            const float* __restrict__ w, const float* __restrict__ bias,
            float* __restrict__ out, const float* __restrict__ addsrc,
            int OC_total, int do_relu) {
  extern __shared__ uint32_t smu[];
  uint32_t* Bst = smu;
  uint32_t* Ah = smu + BST_U;

  const int t = threadIdx.x, lane = t & 31, wid = t >> 5;
  const int gid = lane >> 2, tig = lane & 3;
  const int wm = wid & 1, wn = wid >> 1;

  const int y = blockIdx.x & 255, b = blockIdx.x >> 8;
  const int oc0 = blockIdx.y * 64;
  const int OCv = min(64, OC_total - oc0);
  const int Ktot = NHALF * 576;

  // B fragment base: pair = tig, rows = pair*3 + ky, col = px + kx + 3
  const int rB = tig * (3 * BSTR) + wn * 64 + gid;

  float acc[2][8][4];
#pragma unroll
  for (int f = 0; f < 2; f++)
#pragma unroll
    for (int j = 0; j < 8; j++)
#pragma unroll
      for (int e = 0; e < 4; e++) acc[f][j][e] = 0.f;

  for (int h = 0; h < NHALF; h++) {
    const float* src = (h == 0) ? inA : inB;
    for (int chunk = 0; chunk < 4; chunk++) {
      __syncthreads();  // previous chunk consumed
      const int icg0 = chunk * 16;
      // ---- stage B: 8 pairs x 3 rows x 66 word4 (fp16x2 of ch 2p / 2p+1) ----
      for (int i = t; i < 8 * 3 * 66; i += 256) {
        int p = i / 198, r = i - p * 198;
        int rr = r / 66, q = r - rr * 66;
        int gy = y + rr - 1;
        uint4 u = make_uint4(0u, 0u, 0u, 0u);
        if ((unsigned)gy < 256u && q >= 1 && q <= 64) {
          const float* sp0 =
              src + ((size_t)(b * 64 + icg0 + 2 * p)) * HWc + (size_t)gy * 256;
          const float* sp1 = sp0 + HWc;
          float4 v0 = *(const float4*)(sp0 + q * 4 - 4);
          float4 v1 = *(const float4*)(sp1 + q * 4 - 4);
          u.x = packh2(v0.x, v1.x);
          u.y = packh2(v0.y, v1.y);
          u.z = packh2(v0.z, v1.z);
          u.w = packh2(v0.w, v1.w);
        }
        *(uint4*)&Bst[(p * 3 + rr) * BSTR + q * 4] = u;
      }
      // ---- stage A: 64 m x 72 k-pairs (tap-major), single fp16 ----
      for (int i = t; i < 64 * 72; i += 256) {
        int m = i / 72, k = i - m * 72;
        int tap = k >> 3, p = k & 7;
        float w0 = 0.f, w1 = 0.f;
        if (m < OCv) {
          const float* wp = w + (size_t)(oc0 + m) * Ktot + (h * 64 + icg0) * 9;
          w0 = wp[(2 * p) * 9 + tap];
          w1 = wp[(2 * p + 1) * 9 + tap];
        }
        Ah[m * ASTR + k] = packh2(w0, w1);
      }
      __syncthreads();

      if (wm * 32 < OCv) {
#pragma unroll
        for (int ks = 0; ks < 9; ks++) {
          const int ky = ks / 3, kx = ks % 3;  // compile-time after unroll
          const int rb0 = rB + ky * BSTR + kx + 3;
          const int rb1 = rb0 + 4 * 3 * BSTR;  // pair tig+4
          uint32_t b0[8], b1[8];
#pragma unroll
          for (int j = 0; j < 8; j++) {
            b0[j] = Bst[rb0 + 8 * j];
            b1[j] = Bst[rb1 + 8 * j];
          }
#pragma unroll
          for (int f = 0; f < 2; f++) {
            if (wm * 32 + f * 16 >= OCv) break;
            const int ar = (wm * 32 + f * 16 + gid) * ASTR + ks * 8 + tig;
            uint32_t a0 = Ah[ar], a1 = Ah[ar + 8 * ASTR];
            uint32_t a2 = Ah[ar + 4], a3 = Ah[ar + 8 * ASTR + 4];
#pragma unroll
            for (int j = 0; j < 8; j++) mma16(acc[f][j], a0, a1, a2, a3, b0[j], b1[j]);
          }
        }
      }
    }
  }

  // ---- epilogue: bias, relu, residual; px = wn*64 + j*8 + tig*2 ----
#pragma unroll
  for (int f = 0; f < 2; f++) {
#pragma unroll
    for (int half = 0; half < 2; half++) {
      int m = wm * 32 + f * 16 + gid + half * 8;
      if (m >= OCv) continue;
      int oc = oc0 + m;
      float bv = bias[oc];
      size_t base =
          ((size_t)b * OC_total + oc) * HWc + (size_t)y * 256 + wn * 64 + tig * 2;
      float* op = out + base;
      const float* ap = addsrc ? addsrc + base : nullptr;
#pragma unroll
      for (int j = 0; j < 8; j++) {
        float v0 = acc[f][j][half * 2 + 0] + bv;
        float v1 = acc[f][j][half * 2 + 1] + bv;
        if (do_relu) { v0 = fmaxf(v0, 0.f); v1 = fmaxf(v1, 0.f); }
        if (ap) {
          float2 a2 = *(const float2*)(ap + j * 8);
          v0 += a2.x; v1 += a2.y;
        }
        *(float2*)(op + j * 8) = make_float2(v0, v1);
      }
    }
  }
}

// ---------------- deformable conv (G=8, Cg=8, K=3) ---------------------------
__global__ __launch_bounds__(256) void deform_kernel(
    const float* __restrict__ ref, const float* __restrict__ doff,
    const float* __restrict__ w_def, const float* __restrict__ b_def,
    float* __restrict__ out) {
  const int x = threadIdx.x, y = blockIdx.x, g = blockIdx.y, b = blockIdx.z;
  __shared__ float s_w[8][8][9];
  for (int i = threadIdx.x; i < 576; i += 256) {
    int o = i / 72, r = i - o * 72;
    s_w[o][0][r] = w_def[(g * 8 + o) * 72 + r];
  }
  __syncthreads();
  const float* refg = ref + (b * 64 + g * 8) * HWc;
  const float* offg = doff + (b * 144 + g * 18) * HWc + y * Wc + x;
  float acc[8];
#pragma unroll
  for (int o = 0; o < 8; o++) acc[o] = 0.f;
#pragma unroll 1
  for (int k = 0; k < 9; k++) {
    float dy = offg[(2 * k) * HWc];
    float dx = offg[(2 * k + 1) * HWc];
    float pyf = dy + (float)(y + k / 3 - 1);
    float pxf = dx + (float)(x + k % 3 - 1);
    float fy = floorf(pyf), fx = floorf(pxf);
    int y0 = (int)fy, x0 = (int)fx;
    float ly = pyf - fy, lx = pxf - fx;
    float w00 = (1.f - ly) * (1.f - lx), w01 = (1.f - ly) * lx;
    float w10 = ly * (1.f - lx), w11 = ly * lx;
    bool vy0 = (unsigned)y0 < 256u, vy1 = (unsigned)(y0 + 1) < 256u;
    bool vx0 = (unsigned)x0 < 256u, vx1 = (unsigned)(x0 + 1) < 256u;
    if (!(vy0 && vx0)) w00 = 0.f;
    if (!(vy0 && vx1)) w01 = 0.f;
    if (!(vy1 && vx0)) w10 = 0.f;
    if (!(vy1 && vx1)) w11 = 0.f;
    int cy0 = min(max(y0, 0), 255), cy1 = min(max(y0 + 1, 0), 255);
    int cx0 = min(max(x0, 0), 255), cx1 = min(max(x0 + 1, 0), 255);
    int i00 = cy0 * Wc + cx0, i01 = cy0 * Wc + cx1;
    int i10 = cy1 * Wc + cx0, i11 = cy1 * Wc + cx1;
#pragma unroll
    for (int cch = 0; cch < 8; cch++) {
      const float* rp = refg + cch * HWc;
      float s = w00 * rp[i00] + w01 * rp[i01] + w10 * rp[i10] + w11 * rp[i11];
#pragma unroll
      for (int o = 0; o < 8; o++) acc[o] = fmaf(s, s_w[o][cch][k], acc[o]);
    }
  }
#pragma unroll
  for (int o = 0; o < 8; o++)
    out[(b * 64 + g * 8 + o) * HWc + y * Wc + x] = acc[o] + b_def[g * 8 + o];
}

extern "C" void kernel_launch(void* const* d_in, const int* in_sizes, int n_in,
                              void* d_out, int out_size) {
  const float* offset = (const float*)d_in[0];
  const float* ref    = (const float*)d_in[1];
  const float* w_off  = (const float*)d_in[2];
  const float* b_off  = (const float*)d_in[3];
  const float* w_def  = (const float*)d_in[4];
  const float* b_def  = (const float*)d_in[5];
  const float* w_r1   = (const float*)d_in[6];
  const float* b_r1   = (const float*)d_in[7];
  const float* w_r2   = (const float*)d_in[8];
  const float* b_r2   = (const float*)d_in[9];
  float* out = (float*)d_out;

  float *p_doff, *p_aligned, *p_x1;
  cudaGetSymbolAddress((void**)&p_doff, g_doff);
  cudaGetSymbolAddress((void**)&p_aligned, g_aligned);
  cudaGetSymbolAddress((void**)&p_x1, g_x1);

  cudaFuncSetAttribute(conv3x3_mma<1>, cudaFuncAttributeMaxDynamicSharedMemorySize,
                       (int)SMEM_BYTES);
  cudaFuncSetAttribute(conv3x3_mma<2>, cudaFuncAttributeMaxDynamicSharedMemorySize,
                       (int)SMEM_BYTES);

  // 1) deform_offsets = conv3x3(offset)  64 -> 144 (oc blocks 64/64/16)
  conv3x3_mma<1><<<dim3(512, 3), 256, SMEM_BYTES>>>(offset, nullptr, w_off, b_off,
                                                    p_doff, nullptr, 144, 0);
  // 2) deformable conv
  deform_kernel<<<dim3(256, 8, 2), 256>>>(ref, p_doff, w_def, b_def, p_aligned);
  // 3) x1 = relu(conv3x3(concat(ref, aligned)))  128 -> 64
  conv3x3_mma<2><<<dim3(512, 1), 256, SMEM_BYTES>>>(ref, p_aligned, w_r1, b_r1,
                                                    p_x1, nullptr, 64, 1);
  // 4) out = relu(conv3x3(x1)) + aligned  64 -> 64
  conv3x3_mma<1><<<dim3(512, 1), 256, SMEM_BYTES>>>(p_x1, nullptr, w_r2, b_r2,
                                                    out, p_aligned, 64, 1);
}

// round 12
// speedup vs baseline: 1.1717x; 1.1717x over previous
#include <cuda_runtime.h>
#include <cuda_fp16.h>
#include <cstdint>

__device__ float g_doff[2 * 144 * 256 * 256];
__device__ float g_aligned[2 * 64 * 256 * 256];
__device__ float g_x1[2 * 64 * 256 * 256];

static constexpr int Hc = 256, Wc = 256, HWc = Hc * Wc;

// smem (uint32 words):
//  Bst: 8 channel-PAIRS x 3 rows x 264 (fp16x2: lo=ch even, hi=ch odd)
//  Ah:  64 m x 292 (288 k-pairs for one h-half: col = chunk*72 + tap*8 + p)
static constexpr int BSTR = 264;
static constexpr int BST_U = 8 * 3 * BSTR;    // 6336
static constexpr int ASTR = 292;              // %32 == 4 -> conflict-free frags
static constexpr int AST_U = 64 * ASTR;       // 18688
static constexpr int SMEM_U = BST_U + AST_U;  // 25024
static constexpr size_t SMEM_BYTES = (size_t)SMEM_U * 4;  // 100096 B

__device__ __forceinline__ uint32_t packh2(float lo, float hi) {
  __half2 h = __floats2half2_rn(lo, hi);  // .x = lo half
  return *reinterpret_cast<uint32_t*>(&h);
}
__device__ __forceinline__ void mma16(float* c, uint32_t a0, uint32_t a1,
                                      uint32_t a2, uint32_t a3, uint32_t b0,
                                      uint32_t b1) {
  asm volatile(
      "mma.sync.aligned.m16n8k16.row.col.f32.f16.f16.f32 "
      "{%0,%1,%2,%3}, {%4,%5,%6,%7}, {%8,%9}, {%0,%1,%2,%3};"
      : "+f"(c[0]), "+f"(c[1]), "+f"(c[2]), "+f"(c[3])
      : "r"(a0), "r"(a1), "r"(a2), "r"(a3), "r"(b0), "r"(b1));
}

// CTA: one full image row y (256 px) x 64 output channels.
// 8 warps: warp tile 32m x 64n. K: per h-half, A staged once (288 k-pairs),
// B staged per 16-ic chunk; inner loop interleaves {ldb, mma, mma} per j.
template <int NHALF>  // IC = NHALF*64
__global__ void __launch_bounds__(256, 2)
conv3x3_mma(const float* __restrict__ inA, const float* __restrict__ inB,
            const float* __restrict__ w, const float* __restrict__ bias,
            float* __restrict__ out, const float* __restrict__ addsrc,
            int OC_total, int do_relu) {
  extern __shared__ uint32_t smu[];
  uint32_t* Bst = smu;
  uint32_t* Ah = smu + BST_U;

  const int t = threadIdx.x, lane = t & 31, wid = t >> 5;
  const int gid = lane >> 2, tig = lane & 3;
  const int wm = wid & 1, wn = wid >> 1;

  const int y = blockIdx.x & 255, b = blockIdx.x >> 8;
  const int oc0 = blockIdx.y * 64;
  const int OCv = min(64, OC_total - oc0);
  const int Ktot = NHALF * 576;

  // B fragment base: pair = tig, rows = pair*3 + ky, col = px + kx + 3
  const int rB = tig * (3 * BSTR) + wn * 64 + gid;

  float acc[2][8][4];
#pragma unroll
  for (int f = 0; f < 2; f++)
#pragma unroll
    for (int j = 0; j < 8; j++)
#pragma unroll
      for (int e = 0; e < 4; e++) acc[f][j][e] = 0.f;

  for (int h = 0; h < NHALF; h++) {
    const float* src = (h == 0) ? inA : inB;

    // ---- stage A for this half: 64 m x 288 k-pairs, once ----
    __syncthreads();
    {
      const float* wh = w + (size_t)oc0 * Ktot + h * 576;
      for (int i = t; i < 64 * 288; i += 256) {
        int m = i / 288, c = i - m * 288;
        int chunk = c / 72, r = c - chunk * 72;
        int tap = r >> 3, p = r & 7;
        float w0 = 0.f, w1 = 0.f;
        if (m < OCv) {
          const float* wp = wh + (size_t)m * Ktot + (chunk * 16 + 2 * p) * 9 + tap;
          w0 = wp[0];
          w1 = wp[9];
        }
        Ah[m * ASTR + c] = packh2(w0, w1);
      }
    }

    for (int chunk = 0; chunk < 4; chunk++) {
      __syncthreads();  // previous chunk's B consumed (also covers A stage)
      const int icg0 = chunk * 16;
      // ---- stage B: 8 pairs x 3 rows x 66 word4 (fp16x2 of ch 2p / 2p+1) ----
      for (int i = t; i < 8 * 3 * 66; i += 256) {
        int p = i / 198, r = i - p * 198;
        int rr = r / 66, q = r - rr * 66;
        int gy = y + rr - 1;
        uint4 u = make_uint4(0u, 0u, 0u, 0u);
        if ((unsigned)gy < 256u && q >= 1 && q <= 64) {
          const float* sp0 =
              src + ((size_t)(b * 64 + icg0 + 2 * p)) * HWc + (size_t)gy * 256;
          const float* sp1 = sp0 + HWc;
          float4 v0 = *(const float4*)(sp0 + q * 4 - 4);
          float4 v1 = *(const float4*)(sp1 + q * 4 - 4);
          u.x = packh2(v0.x, v1.x);
          u.y = packh2(v0.y, v1.y);
          u.z = packh2(v0.z, v1.z);
          u.w = packh2(v0.w, v1.w);
        }
        *(uint4*)&Bst[(p * 3 + rr) * BSTR + q * 4] = u;
      }
      __syncthreads();

      if (wm * 32 < OCv) {
        const bool f1ok = (wm * 32 + 16) < OCv;
#pragma unroll
        for (int ks = 0; ks < 9; ks++) {
          const int ky = ks / 3, kx = ks % 3;  // compile-time after unroll
          const int rb0 = rB + ky * BSTR + kx + 3;
          const int rb1 = rb0 + 4 * 3 * BSTR;  // pair tig+4
          // hoist A fragments for both m-frags (8 words)
          const int kcol = chunk * 72 + ks * 8 + tig;
          const int ar0 = (wm * 32 + gid) * ASTR + kcol;
          const int ar1 = (wm * 32 + 16 + gid) * ASTR + kcol;
          uint32_t a00 = Ah[ar0], a01 = Ah[ar0 + 8 * ASTR];
          uint32_t a02 = Ah[ar0 + 4], a03 = Ah[ar0 + 8 * ASTR + 4];
          uint32_t a10 = f1ok ? Ah[ar1] : 0u;
          uint32_t a11 = f1ok ? Ah[ar1 + 8 * ASTR] : 0u;
          uint32_t a12 = f1ok ? Ah[ar1 + 4] : 0u;
          uint32_t a13 = f1ok ? Ah[ar1 + 8 * ASTR + 4] : 0u;
          // interleaved: each b pair feeds both m-frags immediately
#pragma unroll
          for (int j = 0; j < 8; j++) {
            uint32_t b0 = Bst[rb0 + 8 * j];
            uint32_t b1 = Bst[rb1 + 8 * j];
            mma16(acc[0][j], a00, a01, a02, a03, b0, b1);
            if (f1ok) mma16(acc[1][j], a10, a11, a12, a13, b0, b1);
          }
        }
      }
    }
  }

  // ---- epilogue: bias, relu, residual; px = wn*64 + j*8 + tig*2 ----
#pragma unroll
  for (int f = 0; f < 2; f++) {
#pragma unroll
    for (int half = 0; half < 2; half++) {
      int m = wm * 32 + f * 16 + gid + half * 8;
      if (m >= OCv) continue;
      int oc = oc0 + m;
      float bv = bias[oc];
      size_t base =
          ((size_t)b * OC_total + oc) * HWc + (size_t)y * 256 + wn * 64 + tig * 2;
      float* op = out + base;
      const float* ap = addsrc ? addsrc + base : nullptr;
#pragma unroll
      for (int j = 0; j < 8; j++) {
        float v0 = acc[f][j][half * 2 + 0] + bv;
        float v1 = acc[f][j][half * 2 + 1] + bv;
        if (do_relu) { v0 = fmaxf(v0, 0.f); v1 = fmaxf(v1, 0.f); }
        if (ap) {
          float2 a2 = *(const float2*)(ap + j * 8);
          v0 += a2.x; v1 += a2.y;
        }
        *(float2*)(op + j * 8) = make_float2(v0, v1);
      }
    }
  }
}

// ---------------- deformable conv (G=8, Cg=8, K=3) ---------------------------
__global__ __launch_bounds__(256) void deform_kernel(
    const float* __restrict__ ref, const float* __restrict__ doff,
    const float* __restrict__ w_def, const float* __restrict__ b_def,
    float* __restrict__ out) {
  const int x = threadIdx.x, y = blockIdx.x, g = blockIdx.y, b = blockIdx.z;
  __shared__ float s_w[8][8][9];
  for (int i = threadIdx.x; i < 576; i += 256) {
    int o = i / 72, r = i - o * 72;
    s_w[o][0][r] = w_def[(g * 8 + o) * 72 + r];
  }
  __syncthreads();
  const float* refg = ref + (b * 64 + g * 8) * HWc;
  const float* offg = doff + (b * 144 + g * 18) * HWc + y * Wc + x;
  float acc[8];
#pragma unroll
  for (int o = 0; o < 8; o++) acc[o] = 0.f;
#pragma unroll 1
  for (int k = 0; k < 9; k++) {
    float dy = offg[(2 * k) * HWc];
    float dx = offg[(2 * k + 1) * HWc];
    float pyf = dy + (float)(y + k / 3 - 1);
    float pxf = dx + (float)(x + k % 3 - 1);
    float fy = floorf(pyf), fx = floorf(pxf);
    int y0 = (int)fy, x0 = (int)fx;
    float ly = pyf - fy, lx = pxf - fx;
    float w00 = (1.f - ly) * (1.f - lx), w01 = (1.f - ly) * lx;
    float w10 = ly * (1.f - lx), w11 = ly * lx;
    bool vy0 = (unsigned)y0 < 256u, vy1 = (unsigned)(y0 + 1) < 256u;
    bool vx0 = (unsigned)x0 < 256u, vx1 = (unsigned)(x0 + 1) < 256u;
    if (!(vy0 && vx0)) w00 = 0.f;
    if (!(vy0 && vx1)) w01 = 0.f;
    if (!(vy1 && vx0)) w10 = 0.f;
    if (!(vy1 && vx1)) w11 = 0.f;
    int cy0 = min(max(y0, 0), 255), cy1 = min(max(y0 + 1, 0), 255);
    int cx0 = min(max(x0, 0), 255), cx1 = min(max(x0 + 1, 0), 255);
    int i00 = cy0 * Wc + cx0, i01 = cy0 * Wc + cx1;
    int i10 = cy1 * Wc + cx0, i11 = cy1 * Wc + cx1;
#pragma unroll
    for (int cch = 0; cch < 8; cch++) {
      const float* rp = refg + cch * HWc;
      float s = w00 * rp[i00] + w01 * rp[i01] + w10 * rp[i10] + w11 * rp[i11];
#pragma unroll
      for (int o = 0; o < 8; o++) acc[o] = fmaf(s, s_w[o][cch][k], acc[o]);
    }
  }
#pragma unroll
  for (int o = 0; o < 8; o++)
    out[(b * 64 + g * 8 + o) * HWc + y * Wc + x] = acc[o] + b_def[g * 8 + o];
}

extern "C" void kernel_launch(void* const* d_in, const int* in_sizes, int n_in,
                              void* d_out, int out_size) {
  const float* offset = (const float*)d_in[0];
  const float* ref    = (const float*)d_in[1];
  const float* w_off  = (const float*)d_in[2];
  const float* b_off  = (const float*)d_in[3];
  const float* w_def  = (const float*)d_in[4];
  const float* b_def  = (const float*)d_in[5];
  const float* w_r1   = (const float*)d_in[6];
  const float* b_r1   = (const float*)d_in[7];
  const float* w_r2   = (const float*)d_in[8];
  const float* b_r2   = (const float*)d_in[9];
  float* out = (float*)d_out;

  float *p_doff, *p_aligned, *p_x1;
  cudaGetSymbolAddress((void**)&p_doff, g_doff);
  cudaGetSymbolAddress((void**)&p_aligned, g_aligned);
  cudaGetSymbolAddress((void**)&p_x1, g_x1);

  cudaFuncSetAttribute(conv3x3_mma<1>, cudaFuncAttributeMaxDynamicSharedMemorySize,
                       (int)SMEM_BYTES);
  cudaFuncSetAttribute(conv3x3_mma<2>, cudaFuncAttributeMaxDynamicSharedMemorySize,
                       (int)SMEM_BYTES);

  // 1) deform_offsets = conv3x3(offset)  64 -> 144 (oc blocks 64/64/16)
  conv3x3_mma<1><<<dim3(512, 3), 256, SMEM_BYTES>>>(offset, nullptr, w_off, b_off,
                                                    p_doff, nullptr, 144, 0);
  // 2) deformable conv
  deform_kernel<<<dim3(256, 8, 2), 256>>>(ref, p_doff, w_def, b_def, p_aligned);
  // 3) x1 = relu(conv3x3(concat(ref, aligned)))  128 -> 64
  conv3x3_mma<2><<<dim3(512, 1), 256, SMEM_BYTES>>>(ref, p_aligned, w_r1, b_r1,
                                                    p_x1, nullptr, 64, 1);
  // 4) out = relu(conv3x3(x1)) + aligned  64 -> 64
  conv3x3_mma<1><<<dim3(512, 1), 256, SMEM_BYTES>>>(p_x1, nullptr, w_r2, b_r2,
                                                    out, p_aligned, 64, 1);
}

// round 13
// speedup vs baseline: 1.2919x; 1.1026x over previous
#include <cuda_runtime.h>
#include <cuda_fp16.h>
#include <cstdint>

__device__ float g_doff[2 * 144 * 256 * 256];
__device__ float g_aligned[2 * 64 * 256 * 256];
__device__ float g_x1[2 * 64 * 256 * 256];

static constexpr int Hc = 256, Wc = 256, HWc = Hc * Wc;

// smem (uint32 words), per 128-thread CTA (64 oc x 128 px tile):
//  Bst: 8 channel-PAIRS x 3 rows x 136 (fp16x2; col = gx - x0 + 4)
//  Ah:  64 m x 84 (72 k-pairs, tap-major: idx = tap*8 + pair)
static constexpr int BSTR = 136;
static constexpr int BST_U = 8 * 3 * BSTR;    // 3264
static constexpr int ASTR = 84;
static constexpr int AST_U = 64 * ASTR;       // 5376
static constexpr int SMEM_U = BST_U + AST_U;  // 8640
static constexpr size_t SMEM_BYTES = (size_t)SMEM_U * 4;  // 34560 B

__device__ __forceinline__ uint32_t packh2(float lo, float hi) {
  __half2 h = __floats2half2_rn(lo, hi);  // .x = lo half
  return *reinterpret_cast<uint32_t*>(&h);
}
__device__ __forceinline__ void mma16(float* c, uint32_t a0, uint32_t a1,
                                      uint32_t a2, uint32_t a3, uint32_t b0,
                                      uint32_t b1) {
  asm volatile(
      "mma.sync.aligned.m16n8k16.row.col.f32.f16.f16.f32 "
      "{%0,%1,%2,%3}, {%4,%5,%6,%7}, {%8,%9}, {%0,%1,%2,%3};"
      : "+f"(c[0]), "+f"(c[1]), "+f"(c[2]), "+f"(c[3])
      : "r"(a0), "r"(a1), "r"(a2), "r"(a3), "r"(b0), "r"(b1));
}

// CTA (128 thr, 4 warps): 128-px strip of row y x 64 output channels.
// Warp tile 32m x 64n (wm = wid&1, wn = wid>>1). 4 CTAs/SM for overlap.
template <int NHALF>  // IC = NHALF*64
__global__ void __launch_bounds__(128, 4)
conv3x3_mma(const float* __restrict__ inA, const float* __restrict__ inB,
            const float* __restrict__ w, const float* __restrict__ bias,
            float* __restrict__ out, const float* __restrict__ addsrc,
            int OC_total, int do_relu) {
  extern __shared__ uint32_t smu[];
  uint32_t* Bst = smu;
  uint32_t* Ah = smu + BST_U;

  const int t = threadIdx.x, lane = t & 31, wid = t >> 5;
  const int gid = lane >> 2, tig = lane & 3;
  const int wm = wid & 1, wn = wid >> 1;

  const int bx = blockIdx.x;
  const int xt = bx & 1, y = (bx >> 1) & 255, b = bx >> 9;
  const int x0 = xt * 128;
  const int oc0 = blockIdx.y * 64;
  const int OCv = min(64, OC_total - oc0);
  const int Ktot = NHALF * 576;

  // B fragment base: pair = tig, rows = pair*3 + ky, col = px + kx + 3
  const int rB = tig * (3 * BSTR) + wn * 64 + gid;

  float acc[2][8][4];
#pragma unroll
  for (int f = 0; f < 2; f++)
#pragma unroll
    for (int j = 0; j < 8; j++)
#pragma unroll
      for (int e = 0; e < 4; e++) acc[f][j][e] = 0.f;

  for (int h = 0; h < NHALF; h++) {
    const float* src = (h == 0) ? inA : inB;
    for (int chunk = 0; chunk < 4; chunk++) {
      __syncthreads();  // previous chunk consumed
      const int icg0 = chunk * 16;
      // ---- stage B: 8 pairs x 3 rows x 34 word4 (fp16x2 of ch 2p/2p+1) ----
      for (int i = t; i < 8 * 3 * 34; i += 128) {
        int p = i / 102, r = i - p * 102;
        int rr = r / 34, q = r - rr * 34;
        int gy = y + rr - 1;
        int gx0 = x0 + q * 4 - 4;
        uint4 u = make_uint4(0u, 0u, 0u, 0u);
        if ((unsigned)gy < 256u) {
          const float* sp0 =
              src + ((size_t)(b * 64 + icg0 + 2 * p)) * HWc + (size_t)gy * 256;
          const float* sp1 = sp0 + HWc;
          if (gx0 >= 0 && gx0 <= 252) {
            float4 v0 = *(const float4*)(sp0 + gx0);
            float4 v1 = *(const float4*)(sp1 + gx0);
            u.x = packh2(v0.x, v1.x);
            u.y = packh2(v0.y, v1.y);
            u.z = packh2(v0.z, v1.z);
            u.w = packh2(v0.w, v1.w);
          } else {
            uint32_t* pu = &u.x;
#pragma unroll
            for (int e = 0; e < 4; e++) {
              int gx = gx0 + e;
              if ((unsigned)gx < 256u) pu[e] = packh2(sp0[gx], sp1[gx]);
            }
          }
        }
        *(uint4*)&Bst[(p * 3 + rr) * BSTR + q * 4] = u;
      }
      // ---- stage A: 64 m x 72 k-pairs (tap-major), single fp16 ----
      for (int i = t; i < 64 * 72; i += 128) {
        int m = i / 72, k = i - m * 72;
        int tap = k >> 3, p = k & 7;
        float w0 = 0.f, w1 = 0.f;
        if (m < OCv) {
          const float* wp =
              w + (size_t)(oc0 + m) * Ktot + (h * 64 + icg0 + 2 * p) * 9 + tap;
          w0 = wp[0];
          w1 = wp[9];
        }
        Ah[m * ASTR + k] = packh2(w0, w1);
      }
      __syncthreads();

      if (wm * 32 < OCv) {
        const bool f1ok = (wm * 32 + 16) < OCv;
#pragma unroll
        for (int ks = 0; ks < 9; ks++) {
          const int ky = ks / 3, kx = ks % 3;  // compile-time after unroll
          const int rb0 = rB + ky * BSTR + kx + 3;
          const int rb1 = rb0 + 4 * 3 * BSTR;  // pair tig+4
          const int ar0 = (wm * 32 + gid) * ASTR + ks * 8 + tig;
          const int ar1 = ar0 + 16 * ASTR;
          uint32_t a00 = Ah[ar0], a01 = Ah[ar0 + 8 * ASTR];
          uint32_t a02 = Ah[ar0 + 4], a03 = Ah[ar0 + 8 * ASTR + 4];
          uint32_t a10 = f1ok ? Ah[ar1] : 0u;
          uint32_t a11 = f1ok ? Ah[ar1 + 8 * ASTR] : 0u;
          uint32_t a12 = f1ok ? Ah[ar1 + 4] : 0u;
          uint32_t a13 = f1ok ? Ah[ar1 + 8 * ASTR + 4] : 0u;
#pragma unroll
          for (int j = 0; j < 8; j++) {
            uint32_t b0 = Bst[rb0 + 8 * j];
            uint32_t b1 = Bst[rb1 + 8 * j];
            mma16(acc[0][j], a00, a01, a02, a03, b0, b1);
            if (f1ok) mma16(acc[1][j], a10, a11, a12, a13, b0, b1);
          }
        }
      }
    }
  }

  // ---- epilogue: bias, relu, residual; px = x0 + wn*64 + j*8 + tig*2 ----
#pragma unroll
  for (int f = 0; f < 2; f++) {
#pragma unroll
    for (int half = 0; half < 2; half++) {
      int m = wm * 32 + f * 16 + gid + half * 8;
      if (m >= OCv) continue;
      int oc = oc0 + m;
      float bv = bias[oc];
      size_t base = ((size_t)b * OC_total + oc) * HWc + (size_t)y * 256 + x0 +
                    wn * 64 + tig * 2;
      float* op = out + base;
      const float* ap = addsrc ? addsrc + base : nullptr;
#pragma unroll
      for (int j = 0; j < 8; j++) {
        float v0 = acc[f][j][half * 2 + 0] + bv;
        float v1 = acc[f][j][half * 2 + 1] + bv;
        if (do_relu) { v0 = fmaxf(v0, 0.f); v1 = fmaxf(v1, 0.f); }
        if (ap) {
          float2 a2 = *(const float2*)(ap + j * 8);
          v0 += a2.x; v1 += a2.y;
        }
        *(float2*)(op + j * 8) = make_float2(v0, v1);
      }
    }
  }
}

// ---------------- deformable conv (G=8, Cg=8, K=3) ---------------------------
__global__ __launch_bounds__(256) void deform_kernel(
    const float* __restrict__ ref, const float* __restrict__ doff,
    const float* __restrict__ w_def, const float* __restrict__ b_def,
    float* __restrict__ out) {
  const int x = threadIdx.x, y = blockIdx.x, g = blockIdx.y, b = blockIdx.z;
  __shared__ float s_w[8][8][9];
  for (int i = threadIdx.x; i < 576; i += 256) {
    int o = i / 72, r = i - o * 72;
    s_w[o][0][r] = w_def[(g * 8 + o) * 72 + r];
  }
  __syncthreads();
  const float* refg = ref + (b * 64 + g * 8) * HWc;
  const float* offg = doff + (b * 144 + g * 18) * HWc + y * Wc + x;
  float acc[8];
#pragma unroll
  for (int o = 0; o < 8; o++) acc[o] = 0.f;
#pragma unroll 1
  for (int k = 0; k < 9; k++) {
    float dy = offg[(2 * k) * HWc];
    float dx = offg[(2 * k + 1) * HWc];
    float pyf = dy + (float)(y + k / 3 - 1);
    float pxf = dx + (float)(x + k % 3 - 1);
    float fy = floorf(pyf), fx = floorf(pxf);
    int y0 = (int)fy, x0 = (int)fx;
    float ly = pyf - fy, lx = pxf - fx;
    float w00 = (1.f - ly) * (1.f - lx), w01 = (1.f - ly) * lx;
    float w10 = ly * (1.f - lx), w11 = ly * lx;
    bool vy0 = (unsigned)y0 < 256u, vy1 = (unsigned)(y0 + 1) < 256u;
    bool vx0 = (unsigned)x0 < 256u, vx1 = (unsigned)(x0 + 1) < 256u;
    if (!(vy0 && vx0)) w00 = 0.f;
    if (!(vy0 && vx1)) w01 = 0.f;
    if (!(vy1 && vx0)) w10 = 0.f;
    if (!(vy1 && vx1)) w11 = 0.f;
    int cy0 = min(max(y0, 0), 255), cy1 = min(max(y0 + 1, 0), 255);
    int cx0 = min(max(x0, 0), 255), cx1 = min(max(x0 + 1, 0), 255);
    int i00 = cy0 * Wc + cx0, i01 = cy0 * Wc + cx1;
    int i10 = cy1 * Wc + cx0, i11 = cy1 * Wc + cx1;
#pragma unroll
    for (int cch = 0; cch < 8; cch++) {
      const float* rp = refg + cch * HWc;
      float s = w00 * rp[i00] + w01 * rp[i01] + w10 * rp[i10] + w11 * rp[i11];
#pragma unroll
      for (int o = 0; o < 8; o++) acc[o] = fmaf(s, s_w[o][cch][k], acc[o]);
    }
  }
#pragma unroll
  for (int o = 0; o < 8; o++)
    out[(b * 64 + g * 8 + o) * HWc + y * Wc + x] = acc[o] + b_def[g * 8 + o];
}

extern "C" void kernel_launch(void* const* d_in, const int* in_sizes, int n_in,
                              void* d_out, int out_size) {
  const float* offset = (const float*)d_in[0];
  const float* ref    = (const float*)d_in[1];
  const float* w_off  = (const float*)d_in[2];
  const float* b_off  = (const float*)d_in[3];
  const float* w_def  = (const float*)d_in[4];
  const float* b_def  = (const float*)d_in[5];
  const float* w_r1   = (const float*)d_in[6];
  const float* b_r1   = (const float*)d_in[7];
  const float* w_r2   = (const float*)d_in[8];
  const float* b_r2   = (const float*)d_in[9];
  float* out = (float*)d_out;

  float *p_doff, *p_aligned, *p_x1;
  cudaGetSymbolAddress((void**)&p_doff, g_doff);
  cudaGetSymbolAddress((void**)&p_aligned, g_aligned);
  cudaGetSymbolAddress((void**)&p_x1, g_x1);

  cudaFuncSetAttribute(conv3x3_mma<1>, cudaFuncAttributeMaxDynamicSharedMemorySize,
                       (int)SMEM_BYTES);
  cudaFuncSetAttribute(conv3x3_mma<2>, cudaFuncAttributeMaxDynamicSharedMemorySize,
                       (int)SMEM_BYTES);

  // 1) deform_offsets = conv3x3(offset)  64 -> 144 (oc blocks 64/64/16)
  conv3x3_mma<1><<<dim3(1024, 3), 128, SMEM_BYTES>>>(offset, nullptr, w_off, b_off,
                                                     p_doff, nullptr, 144, 0);
  // 2) deformable conv
  deform_kernel<<<dim3(256, 8, 2), 256>>>(ref, p_doff, w_def, b_def, p_aligned);
  // 3) x1 = relu(conv3x3(concat(ref, aligned)))  128 -> 64
  conv3x3_mma<2><<<dim3(1024, 1), 128, SMEM_BYTES>>>(ref, p_aligned, w_r1, b_r1,
                                                     p_x1, nullptr, 64, 1);
  // 4) out = relu(conv3x3(x1)) + aligned  64 -> 64
  conv3x3_mma<1><<<dim3(1024, 1), 128, SMEM_BYTES>>>(p_x1, nullptr, w_r2, b_r2,
                                                     out, p_aligned, 64, 1);
}

// round 14
// speedup vs baseline: 1.5484x; 1.1986x over previous
#include <cuda_runtime.h>
#include <cuda_fp16.h>
#include <cstdint>

__device__ float g_doff[2 * 144 * 256 * 256];
__device__ float g_aligned[2 * 64 * 256 * 256];
__device__ float g_x1[2 * 64 * 256 * 256];
// packed fp16x2 activations: [b][pair(32)][HW]
__device__ uint32_t g_off16[2 * 32 * 65536];
__device__ uint32_t g_ref16[2 * 32 * 65536];
__device__ uint32_t g_al16[2 * 32 * 65536];
__device__ uint32_t g_x116[2 * 32 * 65536];
// packed fp16x2 weights (Ah layout): [oc][NHALF*288]
__device__ uint32_t g_wpk_off[144 * 288];
__device__ uint32_t g_wpk_r1[64 * 576];
__device__ uint32_t g_wpk_r2[64 * 288];

static constexpr int Hc = 256, Wc = 256, HWc = Hc * Wc;

static constexpr int BSTR = 136;
static constexpr int BST_U = 8 * 3 * BSTR;    // 3264
static constexpr int ASTR = 84;
static constexpr int AST_U = 64 * ASTR;       // 5376
static constexpr int SMEM_U = BST_U + AST_U;  // 8640
static constexpr size_t SMEM_BYTES = (size_t)SMEM_U * 4;  // 34560 B

__device__ __forceinline__ uint32_t packh2(float lo, float hi) {
  __half2 h = __floats2half2_rn(lo, hi);
  return *reinterpret_cast<uint32_t*>(&h);
}
__device__ __forceinline__ void mma16(float* c, uint32_t a0, uint32_t a1,
                                      uint32_t a2, uint32_t a3, uint32_t b0,
                                      uint32_t b1) {
  asm volatile(
      "mma.sync.aligned.m16n8k16.row.col.f32.f16.f16.f32 "
      "{%0,%1,%2,%3}, {%4,%5,%6,%7}, {%8,%9}, {%0,%1,%2,%3};"
      : "+f"(c[0]), "+f"(c[1]), "+f"(c[2]), "+f"(c[3])
      : "r"(a0), "r"(a1), "r"(a2), "r"(a3), "r"(b0), "r"(b1));
}

// ---- prep: pack fp32 weights into fp16x2 Ah layout -------------------------
__global__ void pack_w_kernel(const float* __restrict__ w,
                              uint32_t* __restrict__ outp, int OC, int NHALF) {
  int idx = blockIdx.x * 256 + threadIdx.x;
  int KP = NHALF * 288;
  if (idx >= OC * KP) return;
  int oc = idx / KP, c = idx - oc * KP;
  int h = c / 288, r = c - h * 288;
  int chunk = r / 72, r2 = r - chunk * 72;
  int tap = r2 >> 3, p = r2 & 7;
  int Ktot = NHALF * 576;
  const float* wp = w + (size_t)oc * Ktot + (h * 64 + chunk * 16 + 2 * p) * 9 + tap;
  outp[idx] = packh2(wp[0], wp[9]);
}

// ---- prep: pack fp32 activations [b][64][HW] -> fp16x2 [b][32][HW] ---------
__global__ void pack_act_kernel(const float* __restrict__ in,
                                uint32_t* __restrict__ outp) {
  int i = blockIdx.x * 256 + threadIdx.x;  // uint4 index within HW/4
  int p = blockIdx.y, b = blockIdx.z;
  float4 v0 = *((const float4*)(in + ((size_t)(b * 64 + 2 * p)) * HWc) + i);
  float4 v1 = *((const float4*)(in + ((size_t)(b * 64 + 2 * p + 1)) * HWc) + i);
  uint4 u;
  u.x = packh2(v0.x, v1.x);
  u.y = packh2(v0.y, v1.y);
  u.z = packh2(v0.z, v1.z);
  u.w = packh2(v0.w, v1.w);
  *((uint4*)(outp + ((size_t)(b * 32 + p)) * HWc) + i) = u;
}

// CTA (128 thr, 4 warps): 128-px strip of row y x 64 output channels.
// All inputs pre-packed fp16x2; staging is pure aligned copies.
template <int NHALF>  // IC = NHALF*64
__global__ void __launch_bounds__(128, 4)
conv3x3_mma(const uint32_t* __restrict__ inA16, const uint32_t* __restrict__ inB16,
            const uint32_t* __restrict__ wpk, const float* __restrict__ bias,
            float* __restrict__ out, const float* __restrict__ addsrc,
            int OC_total, int do_relu) {
  extern __shared__ uint32_t smu[];
  uint32_t* Bst = smu;
  uint32_t* Ah = smu + BST_U;

  const int t = threadIdx.x, lane = t & 31, wid = t >> 5;
  const int gid = lane >> 2, tig = lane & 3;
  const int wm = wid & 1, wn = wid >> 1;

  const int bx = blockIdx.x;
  const int xt = bx & 1, y = (bx >> 1) & 255, b = bx >> 9;
  const int x0 = xt * 128;
  const int oc0 = blockIdx.y * 64;
  const int OCv = min(64, OC_total - oc0);
  const int KPW = NHALF * 288;

  const int rB = tig * (3 * BSTR) + wn * 64 + gid;

  float acc[2][8][4];
#pragma unroll
  for (int f = 0; f < 2; f++)
#pragma unroll
    for (int j = 0; j < 8; j++)
#pragma unroll
      for (int e = 0; e < 4; e++) acc[f][j][e] = 0.f;

  for (int h = 0; h < NHALF; h++) {
    const uint32_t* src = (h == 0) ? inA16 : inB16;
    for (int chunk = 0; chunk < 4; chunk++) {
      __syncthreads();  // previous chunk consumed
      // ---- stage B: 8 pairs x 3 rows x 34 uint4 (pure copy) ----
      for (int i = t; i < 8 * 3 * 34; i += 128) {
        int p = i / 102, r = i - p * 102;
        int rr = r / 34, q = r - rr * 34;
        int gy = y + rr - 1;
        int gx0 = x0 + q * 4 - 4;
        uint4 u = make_uint4(0u, 0u, 0u, 0u);
        if ((unsigned)gy < 256u && gx0 >= 0 && gx0 <= 252) {
          u = *(const uint4*)(src + ((size_t)(b * 32 + chunk * 8 + p)) * HWc +
                              (size_t)gy * 256 + gx0);
        }
        *(uint4*)&Bst[(p * 3 + rr) * BSTR + q * 4] = u;
      }
      // ---- stage A: 64 m x 18 uint4 (pre-packed, pure copy) ----
      for (int i = t; i < 64 * 18; i += 128) {
        int m = i / 18, q4 = i - m * 18;
        uint4 u = make_uint4(0u, 0u, 0u, 0u);
        if (m < OCv)
          u = *(const uint4*)(wpk + (size_t)(oc0 + m) * KPW + h * 288 +
                              chunk * 72 + q4 * 4);
        *(uint4*)&Ah[m * ASTR + q4 * 4] = u;
      }
      __syncthreads();

      if (wm * 32 < OCv) {
        const bool f1ok = (wm * 32 + 16) < OCv;
#pragma unroll
        for (int ks = 0; ks < 9; ks++) {
          const int ky = ks / 3, kx = ks % 3;
          const int rb0 = rB + ky * BSTR + kx + 3;
          const int rb1 = rb0 + 4 * 3 * BSTR;
          const int ar0 = (wm * 32 + gid) * ASTR + ks * 8 + tig;
          const int ar1 = ar0 + 16 * ASTR;
          uint32_t a00 = Ah[ar0], a01 = Ah[ar0 + 8 * ASTR];
          uint32_t a02 = Ah[ar0 + 4], a03 = Ah[ar0 + 8 * ASTR + 4];
          uint32_t a10 = f1ok ? Ah[ar1] : 0u;
          uint32_t a11 = f1ok ? Ah[ar1 + 8 * ASTR] : 0u;
          uint32_t a12 = f1ok ? Ah[ar1 + 4] : 0u;
          uint32_t a13 = f1ok ? Ah[ar1 + 8 * ASTR + 4] : 0u;
#pragma unroll
          for (int j = 0; j < 8; j++) {
            uint32_t b0 = Bst[rb0 + 8 * j];
            uint32_t b1 = Bst[rb1 + 8 * j];
            mma16(acc[0][j], a00, a01, a02, a03, b0, b1);
            if (f1ok) mma16(acc[1][j], a10, a11, a12, a13, b0, b1);
          }
        }
      }
    }
  }

  // ---- epilogue ----
#pragma unroll
  for (int f = 0; f < 2; f++) {
#pragma unroll
    for (int half = 0; half < 2; half++) {
      int m = wm * 32 + f * 16 + gid + half * 8;
      if (m >= OCv) continue;
      int oc = oc0 + m;
      float bv = bias[oc];
      size_t base = ((size_t)b * OC_total + oc) * HWc + (size_t)y * 256 + x0 +
                    wn * 64 + tig * 2;
      float* op = out + base;
      const float* ap = addsrc ? addsrc + base : nullptr;
#pragma unroll
      for (int j = 0; j < 8; j++) {
        float v0 = acc[f][j][half * 2 + 0] + bv;
        float v1 = acc[f][j][half * 2 + 1] + bv;
        if (do_relu) { v0 = fmaxf(v0, 0.f); v1 = fmaxf(v1, 0.f); }
        if (ap) {
          float2 a2 = *(const float2*)(ap + j * 8);
          v0 += a2.x; v1 += a2.y;
        }
        *(float2*)(op + j * 8) = make_float2(v0, v1);
      }
    }
  }
}

// ---------------- deformable conv (G=8, Cg=8, K=3) ---------------------------
__global__ __launch_bounds__(256) void deform_kernel(
    const float* __restrict__ ref, const float* __restrict__ doff,
    const float* __restrict__ w_def, const float* __restrict__ b_def,
    float* __restrict__ out) {
  const int x = threadIdx.x, y = blockIdx.x, g = blockIdx.y, b = blockIdx.z;
  __shared__ float s_w[8][8][9];
  for (int i = threadIdx.x; i < 576; i += 256) {
    int o = i / 72, r = i - o * 72;
    s_w[o][0][r] = w_def[(g * 8 + o) * 72 + r];
  }
  __syncthreads();
  const float* refg = ref + (b * 64 + g * 8) * HWc;
  const float* offg = doff + (b * 144 + g * 18) * HWc + y * Wc + x;
  float acc[8];
#pragma unroll
  for (int o = 0; o < 8; o++) acc[o] = 0.f;
#pragma unroll 1
  for (int k = 0; k < 9; k++) {
    float dy = offg[(2 * k) * HWc];
    float dx = offg[(2 * k + 1) * HWc];
    float pyf = dy + (float)(y + k / 3 - 1);
    float pxf = dx + (float)(x + k % 3 - 1);
    float fy = floorf(pyf), fx = floorf(pxf);
    int y0 = (int)fy, x0 = (int)fx;
    float ly = pyf - fy, lx = pxf - fx;
    float w00 = (1.f - ly) * (1.f - lx), w01 = (1.f - ly) * lx;
    float w10 = ly * (1.f - lx), w11 = ly * lx;
    bool vy0 = (unsigned)y0 < 256u, vy1 = (unsigned)(y0 + 1) < 256u;
    bool vx0 = (unsigned)x0 < 256u, vx1 = (unsigned)(x0 + 1) < 256u;
    if (!(vy0 && vx0)) w00 = 0.f;
    if (!(vy0 && vx1)) w01 = 0.f;
    if (!(vy1 && vx0)) w10 = 0.f;
    if (!(vy1 && vx1)) w11 = 0.f;
    int cy0 = min(max(y0, 0), 255), cy1 = min(max(y0 + 1, 0), 255);
    int cx0 = min(max(x0, 0), 255), cx1 = min(max(x0 + 1, 0), 255);
    int i00 = cy0 * Wc + cx0, i01 = cy0 * Wc + cx1;
    int i10 = cy1 * Wc + cx0, i11 = cy1 * Wc + cx1;
#pragma unroll
    for (int cch = 0; cch < 8; cch++) {
      const float* rp = refg + cch * HWc;
      float s = w00 * rp[i00] + w01 * rp[i01] + w10 * rp[i10] + w11 * rp[i11];
#pragma unroll
      for (int o = 0; o < 8; o++) acc[o] = fmaf(s, s_w[o][cch][k], acc[o]);
    }
  }
#pragma unroll
  for (int o = 0; o < 8; o++)
    out[(b * 64 + g * 8 + o) * HWc + y * Wc + x] = acc[o] + b_def[g * 8 + o];
}

extern "C" void kernel_launch(void* const* d_in, const int* in_sizes, int n_in,
                              void* d_out, int out_size) {
  const float* offset = (const float*)d_in[0];
  const float* ref    = (const float*)d_in[1];
  const float* w_off  = (const float*)d_in[2];
  const float* b_off  = (const float*)d_in[3];
  const float* w_def  = (const float*)d_in[4];
  const float* b_def  = (const float*)d_in[5];
  const float* w_r1   = (const float*)d_in[6];
  const float* b_r1   = (const float*)d_in[7];
  const float* w_r2   = (const float*)d_in[8];
  const float* b_r2   = (const float*)d_in[9];
  float* out = (float*)d_out;

  float *p_doff, *p_aligned, *p_x1;
  uint32_t *p_off16, *p_ref16, *p_al16, *p_x116;
  uint32_t *p_woff, *p_wr1, *p_wr2;
  cudaGetSymbolAddress((void**)&p_doff, g_doff);
  cudaGetSymbolAddress((void**)&p_aligned, g_aligned);
  cudaGetSymbolAddress((void**)&p_x1, g_x1);
  cudaGetSymbolAddress((void**)&p_off16, g_off16);
  cudaGetSymbolAddress((void**)&p_ref16, g_ref16);
  cudaGetSymbolAddress((void**)&p_al16, g_al16);
  cudaGetSymbolAddress((void**)&p_x116, g_x116);
  cudaGetSymbolAddress((void**)&p_woff, g_wpk_off);
  cudaGetSymbolAddress((void**)&p_wr1, g_wpk_r1);
  cudaGetSymbolAddress((void**)&p_wr2, g_wpk_r2);

  cudaFuncSetAttribute(conv3x3_mma<1>, cudaFuncAttributeMaxDynamicSharedMemorySize,
                       (int)SMEM_BYTES);
  cudaFuncSetAttribute(conv3x3_mma<2>, cudaFuncAttributeMaxDynamicSharedMemorySize,
                       (int)SMEM_BYTES);

  // prep: pack weights + input activations
  pack_w_kernel<<<(144 * 288 + 255) / 256, 256>>>(w_off, p_woff, 144, 1);
  pack_w_kernel<<<(64 * 576 + 255) / 256, 256>>>(w_r1, p_wr1, 64, 2);
  pack_w_kernel<<<(64 * 288 + 255) / 256, 256>>>(w_r2, p_wr2, 64, 1);
  pack_act_kernel<<<dim3(64, 32, 2), 256>>>(offset, p_off16);
  pack_act_kernel<<<dim3(64, 32, 2), 256>>>(ref, p_ref16);

  // 1) deform_offsets = conv3x3(offset)  64 -> 144
  conv3x3_mma<1><<<dim3(1024, 3), 128, SMEM_BYTES>>>(p_off16, nullptr, p_woff,
                                                     b_off, p_doff, nullptr, 144, 0);
  // 2) deformable conv
  deform_kernel<<<dim3(256, 8, 2), 256>>>(ref, p_doff, w_def, b_def, p_aligned);
  pack_act_kernel<<<dim3(64, 32, 2), 256>>>(p_aligned, p_al16);
  // 3) x1 = relu(conv3x3(concat(ref, aligned)))  128 -> 64
  conv3x3_mma<2><<<dim3(1024, 1), 128, SMEM_BYTES>>>(p_ref16, p_al16, p_wr1,
                                                     b_r1, p_x1, nullptr, 64, 1);
  pack_act_kernel<<<dim3(64, 32, 2), 256>>>(p_x1, p_x116);
  // 4) out = relu(conv3x3(x1)) + aligned  64 -> 64
  conv3x3_mma<1><<<dim3(1024, 1), 128, SMEM_BYTES>>>(p_x116, nullptr, p_wr2,
                                                     b_r2, out, p_aligned, 64, 1);
}

// round 15
// speedup vs baseline: 1.6272x; 1.0509x over previous
#include <cuda_runtime.h>
#include <cuda_fp16.h>
#include <cstdint>

__device__ float g_doff[2 * 144 * 256 * 256];
__device__ float g_aligned[2 * 64 * 256 * 256];
__device__ float g_x1[2 * 64 * 256 * 256];
// packed fp16x2 activations: [b][pair(32)][HW]
__device__ uint32_t g_off16[2 * 32 * 65536];
__device__ uint32_t g_ref16[2 * 32 * 65536];
__device__ uint32_t g_al16[2 * 32 * 65536];
__device__ uint32_t g_x116[2 * 32 * 65536];
// packed fp16x2 weights (Ah layout): [oc][NHALF*288]
__device__ uint32_t g_wpk_off[144 * 288];
__device__ uint32_t g_wpk_r1[64 * 576];
__device__ uint32_t g_wpk_r2[64 * 288];

static constexpr int Hc = 256, Wc = 256, HWc = Hc * Wc;

static constexpr int BSTR = 136;
static constexpr int BST_U = 8 * 3 * BSTR;  // 3264 words per buffer
static constexpr int ASTR = 84;
static constexpr int AST_U = 64 * ASTR;     // 5376 words per buffer
static constexpr int SMEM_U = 2 * BST_U + 2 * AST_U;        // 17280
static constexpr size_t SMEM_BYTES = (size_t)SMEM_U * 4;    // 69120 B

__device__ __forceinline__ uint32_t packh2(float lo, float hi) {
  __half2 h = __floats2half2_rn(lo, hi);
  return *reinterpret_cast<uint32_t*>(&h);
}
__device__ __forceinline__ void mma16(float* c, uint32_t a0, uint32_t a1,
                                      uint32_t a2, uint32_t a3, uint32_t b0,
                                      uint32_t b1) {
  asm volatile(
      "mma.sync.aligned.m16n8k16.row.col.f32.f16.f16.f32 "
      "{%0,%1,%2,%3}, {%4,%5,%6,%7}, {%8,%9}, {%0,%1,%2,%3};"
      : "+f"(c[0]), "+f"(c[1]), "+f"(c[2]), "+f"(c[3])
      : "r"(a0), "r"(a1), "r"(a2), "r"(a3), "r"(b0), "r"(b1));
}
__device__ __forceinline__ void cp16(uint32_t dst, const void* src, int sz) {
  asm volatile("cp.async.cg.shared.global [%0], [%1], 16, %2;"
               :: "r"(dst), "l"(src), "r"(sz) : "memory");
}

// ---- prep: pack fp32 weights into fp16x2 Ah layout -------------------------
__global__ void pack_w_kernel(const float* __restrict__ w,
                              uint32_t* __restrict__ outp, int OC, int NHALF) {
  int idx = blockIdx.x * 256 + threadIdx.x;
  int KP = NHALF * 288;
  if (idx >= OC * KP) return;
  int oc = idx / KP, c = idx - oc * KP;
  int h = c / 288, r = c - h * 288;
  int chunk = r / 72, r2 = r - chunk * 72;
  int tap = r2 >> 3, p = r2 & 7;
  int Ktot = NHALF * 576;
  const float* wp = w + (size_t)oc * Ktot + (h * 64 + chunk * 16 + 2 * p) * 9 + tap;
  outp[idx] = packh2(wp[0], wp[9]);
}

// ---- prep: pack fp32 activations [b][64][HW] -> fp16x2 [b][32][HW] ---------
__global__ void pack_act_kernel(const float* __restrict__ in,
                                uint32_t* __restrict__ outp) {
  int i = blockIdx.x * 256 + threadIdx.x;
  int p = blockIdx.y, b = blockIdx.z;
  float4 v0 = *((const float4*)(in + ((size_t)(b * 64 + 2 * p)) * HWc) + i);
  float4 v1 = *((const float4*)(in + ((size_t)(b * 64 + 2 * p + 1)) * HWc) + i);
  uint4 u;
  u.x = packh2(v0.x, v1.x);
  u.y = packh2(v0.y, v1.y);
  u.z = packh2(v0.z, v1.z);
  u.w = packh2(v0.w, v1.w);
  *((uint4*)(outp + ((size_t)(b * 32 + p)) * HWc) + i) = u;
}

// CTA (128 thr, 4 warps): 128-px strip of row y x 64 output channels.
// 2-stage cp.async pipeline: chunk c+1 staged while chunk c runs MMAs.
template <int NHALF>  // IC = NHALF*64
__global__ void __launch_bounds__(128, 3)
conv3x3_mma(const uint32_t* __restrict__ inA16, const uint32_t* __restrict__ inB16,
            const uint32_t* __restrict__ wpk, const float* __restrict__ bias,
            float* __restrict__ out, const float* __restrict__ addsrc,
            int OC_total, int do_relu) {
  extern __shared__ uint32_t smu[];
  // layout: [B0 | B1 | A0 | A1]
  uint32_t* Bbuf[2] = {smu, smu + BST_U};
  uint32_t* Abuf[2] = {smu + 2 * BST_U, smu + 2 * BST_U + AST_U};
  const uint32_t smem_base = (uint32_t)__cvta_generic_to_shared(smu);
  const uint32_t Baddr[2] = {smem_base, smem_base + BST_U * 4};
  const uint32_t Aaddr[2] = {smem_base + 2 * BST_U * 4,
                             smem_base + (2 * BST_U + AST_U) * 4};

  const int t = threadIdx.x, lane = t & 31, wid = t >> 5;
  const int gid = lane >> 2, tig = lane & 3;
  const int wm = wid & 1, wn = wid >> 1;

  const int bx = blockIdx.x;
  const int xt = bx & 1, y = (bx >> 1) & 255, b = bx >> 9;
  const int x0 = xt * 128;
  const int oc0 = blockIdx.y * 64;
  const int OCv = min(64, OC_total - oc0);
  const int KPW = NHALF * 288;
  const int NC = NHALF * 4;

  const int rB = tig * (3 * BSTR) + wn * 64 + gid;

  float acc[2][8][4];
#pragma unroll
  for (int f = 0; f < 2; f++)
#pragma unroll
    for (int j = 0; j < 8; j++)
#pragma unroll
      for (int e = 0; e < 4; e++) acc[f][j][e] = 0.f;

  // ---- chunk stage via cp.async (pure 16B copies, zfill for OOB) ----
  auto issue_chunk = [&](int cc, int buf) {
    const uint32_t* src = ((cc >> 2) == 0) ? inA16 : inB16;
    const int chunk = cc & 3;
    // B: 8 pairs x 3 rows x 34 uint4
    for (int i = t; i < 8 * 3 * 34; i += 128) {
      int p = i / 102, r = i - p * 102;
      int rr = r / 34, q = r - rr * 34;
      int gy = y + rr - 1;
      int gx0 = x0 + q * 4 - 4;
      bool ok = ((unsigned)gy < 256u) && gx0 >= 0 && gx0 <= 252;
      const uint32_t* sp = src + ((size_t)(b * 32 + chunk * 8 + p)) * HWc +
                           (size_t)(ok ? gy : 0) * 256 + (ok ? gx0 : 0);
      cp16(Baddr[buf] + ((p * 3 + rr) * BSTR + q * 4) * 4, sp, ok ? 16 : 0);
    }
    // A: 64 m x 18 uint4
    for (int i = t; i < 64 * 18; i += 128) {
      int m = i / 18, q4 = i - m * 18;
      bool ok = m < OCv;
      const uint32_t* sp = wpk + (size_t)(oc0 + (ok ? m : 0)) * KPW +
                           (cc >> 2) * 288 + chunk * 72 + q4 * 4;
      cp16(Aaddr[buf] + (m * ASTR + q4 * 4) * 4, sp, ok ? 16 : 0);
    }
    asm volatile("cp.async.commit_group;" ::: "memory");
  };

  issue_chunk(0, 0);

  for (int cc = 0; cc < NC; cc++) {
    __syncthreads();  // prior chunk's MMA reads complete before buffer reuse
    if (cc + 1 < NC) {
      issue_chunk(cc + 1, (cc + 1) & 1);
      asm volatile("cp.async.wait_group 1;" ::: "memory");
    } else {
      asm volatile("cp.async.wait_group 0;" ::: "memory");
    }
    __syncthreads();

    const uint32_t* Bst = Bbuf[cc & 1];
    const uint32_t* Ah = Abuf[cc & 1];
    if (wm * 32 < OCv) {
      const bool f1ok = (wm * 32 + 16) < OCv;
#pragma unroll
      for (int ks = 0; ks < 9; ks++) {
        const int ky = ks / 3, kx = ks % 3;
        const int rb0 = rB + ky * BSTR + kx + 3;
        const int rb1 = rb0 + 4 * 3 * BSTR;
        const int ar0 = (wm * 32 + gid) * ASTR + ks * 8 + tig;
        const int ar1 = ar0 + 16 * ASTR;
        uint32_t a00 = Ah[ar0], a01 = Ah[ar0 + 8 * ASTR];
        uint32_t a02 = Ah[ar0 + 4], a03 = Ah[ar0 + 8 * ASTR + 4];
        uint32_t a10 = f1ok ? Ah[ar1] : 0u;
        uint32_t a11 = f1ok ? Ah[ar1 + 8 * ASTR] : 0u;
        uint32_t a12 = f1ok ? Ah[ar1 + 4] : 0u;
        uint32_t a13 = f1ok ? Ah[ar1 + 8 * ASTR + 4] : 0u;
#pragma unroll
        for (int j = 0; j < 8; j++) {
          uint32_t b0 = Bst[rb0 + 8 * j];
          uint32_t b1 = Bst[rb1 + 8 * j];
          mma16(acc[0][j], a00, a01, a02, a03, b0, b1);
          if (f1ok) mma16(acc[1][j], a10, a11, a12, a13, b0, b1);
        }
      }
    }
  }

  // ---- epilogue ----
#pragma unroll
  for (int f = 0; f < 2; f++) {
#pragma unroll
    for (int half = 0; half < 2; half++) {
      int m = wm * 32 + f * 16 + gid + half * 8;
      if (m >= OCv) continue;
      int oc = oc0 + m;
      float bv = bias[oc];
      size_t base = ((size_t)b * OC_total + oc) * HWc + (size_t)y * 256 + x0 +
                    wn * 64 + tig * 2;
      float* op = out + base;
      const float* ap = addsrc ? addsrc + base : nullptr;
#pragma unroll
      for (int j = 0; j < 8; j++) {
        float v0 = acc[f][j][half * 2 + 0] + bv;
        float v1 = acc[f][j][half * 2 + 1] + bv;
        if (do_relu) { v0 = fmaxf(v0, 0.f); v1 = fmaxf(v1, 0.f); }
        if (ap) {
          float2 a2 = *(const float2*)(ap + j * 8);
          v0 += a2.x; v1 += a2.y;
        }
        *(float2*)(op + j * 8) = make_float2(v0, v1);
      }
    }
  }
}

// ---------------- deformable conv (G=8, Cg=8, K=3) ---------------------------
__global__ __launch_bounds__(256) void deform_kernel(
    const float* __restrict__ ref, const float* __restrict__ doff,
    const float* __restrict__ w_def, const float* __restrict__ b_def,
    float* __restrict__ out) {
  const int x = threadIdx.x, y = blockIdx.x, g = blockIdx.y, b = blockIdx.z;
  __shared__ float s_w[8][8][9];
  for (int i = threadIdx.x; i < 576; i += 256) {
    int o = i / 72, r = i - o * 72;
    s_w[o][0][r] = w_def[(g * 8 + o) * 72 + r];
  }
  __syncthreads();
  const float* refg = ref + (b * 64 + g * 8) * HWc;
  const float* offg = doff + (b * 144 + g * 18) * HWc + y * Wc + x;
  float acc[8];
#pragma unroll
  for (int o = 0; o < 8; o++) acc[o] = 0.f;
#pragma unroll 1
  for (int k = 0; k < 9; k++) {
    float dy = offg[(2 * k) * HWc];
    float dx = offg[(2 * k + 1) * HWc];
    float pyf = dy + (float)(y + k / 3 - 1);
    float pxf = dx + (float)(x + k % 3 - 1);
    float fy = floorf(pyf), fx = floorf(pxf);
    int y0 = (int)fy, x0 = (int)fx;
    float ly = pyf - fy, lx = pxf - fx;
    float w00 = (1.f - ly) * (1.f - lx), w01 = (1.f - ly) * lx;
    float w10 = ly * (1.f - lx), w11 = ly * lx;
    bool vy0 = (unsigned)y0 < 256u, vy1 = (unsigned)(y0 + 1) < 256u;
    bool vx0 = (unsigned)x0 < 256u, vx1 = (unsigned)(x0 + 1) < 256u;
    if (!(vy0 && vx0)) w00 = 0.f;
    if (!(vy0 && vx1)) w01 = 0.f;
    if (!(vy1 && vx0)) w10 = 0.f;
    if (!(vy1 && vx1)) w11 = 0.f;
    int cy0 = min(max(y0, 0), 255), cy1 = min(max(y0 + 1, 0), 255);
    int cx0 = min(max(x0, 0), 255), cx1 = min(max(x0 + 1, 0), 255);
    int i00 = cy0 * Wc + cx0, i01 = cy0 * Wc + cx1;
    int i10 = cy1 * Wc + cx0, i11 = cy1 * Wc + cx1;
#pragma unroll
    for (int cch = 0; cch < 8; cch++) {
      const float* rp = refg + cch * HWc;
      float s = w00 * rp[i00] + w01 * rp[i01] + w10 * rp[i10] + w11 * rp[i11];
#pragma unroll
      for (int o = 0; o < 8; o++) acc[o] = fmaf(s, s_w[o][cch][k], acc[o]);
    }
  }
#pragma unroll
  for (int o = 0; o < 8; o++)
    out[(b * 64 + g * 8 + o) * HWc + y * Wc + x] = acc[o] + b_def[g * 8 + o];
}

extern "C" void kernel_launch(void* const* d_in, const int* in_sizes, int n_in,
                              void* d_out, int out_size) {
  const float* offset = (const float*)d_in[0];
  const float* ref    = (const float*)d_in[1];
  const float* w_off  = (const float*)d_in[2];
  const float* b_off  = (const float*)d_in[3];
  const float* w_def  = (const float*)d_in[4];
  const float* b_def  = (const float*)d_in[5];
  const float* w_r1   = (const float*)d_in[6];
  const float* b_r1   = (const float*)d_in[7];
  const float* w_r2   = (const float*)d_in[8];
  const float* b_r2   = (const float*)d_in[9];
  float* out = (float*)d_out;

  float *p_doff, *p_aligned, *p_x1;
  uint32_t *p_off16, *p_ref16, *p_al16, *p_x116;
  uint32_t *p_woff, *p_wr1, *p_wr2;
  cudaGetSymbolAddress((void**)&p_doff, g_doff);
  cudaGetSymbolAddress((void**)&p_aligned, g_aligned);
  cudaGetSymbolAddress((void**)&p_x1, g_x1);
  cudaGetSymbolAddress((void**)&p_off16, g_off16);
  cudaGetSymbolAddress((void**)&p_ref16, g_ref16);
  cudaGetSymbolAddress((void**)&p_al16, g_al16);
  cudaGetSymbolAddress((void**)&p_x116, g_x116);
  cudaGetSymbolAddress((void**)&p_woff, g_wpk_off);
  cudaGetSymbolAddress((void**)&p_wr1, g_wpk_r1);
  cudaGetSymbolAddress((void**)&p_wr2, g_wpk_r2);

  cudaFuncSetAttribute(conv3x3_mma<1>, cudaFuncAttributeMaxDynamicSharedMemorySize,
                       (int)SMEM_BYTES);
  cudaFuncSetAttribute(conv3x3_mma<2>, cudaFuncAttributeMaxDynamicSharedMemorySize,
                       (int)SMEM_BYTES);

  // prep: pack weights + input activations
  pack_w_kernel<<<(144 * 288 + 255) / 256, 256>>>(w_off, p_woff, 144, 1);
  pack_w_kernel<<<(64 * 576 + 255) / 256, 256>>>(w_r1, p_wr1, 64, 2);
  pack_w_kernel<<<(64 * 288 + 255) / 256, 256>>>(w_r2, p_wr2, 64, 1);
  pack_act_kernel<<<dim3(64, 32, 2), 256>>>(offset, p_off16);
  pack_act_kernel<<<dim3(64, 32, 2), 256>>>(ref, p_ref16);

  // 1) deform_offsets = conv3x3(offset)  64 -> 144
  conv3x3_mma<1><<<dim3(1024, 3), 128, SMEM_BYTES>>>(p_off16, nullptr, p_woff,
                                                     b_off, p_doff, nullptr, 144, 0);
  // 2) deformable conv
  deform_kernel<<<dim3(256, 8, 2), 256>>>(ref, p_doff, w_def, b_def, p_aligned);
  pack_act_kernel<<<dim3(64, 32, 2), 256>>>(p_aligned, p_al16);
  // 3) x1 = relu(conv3x3(concat(ref, aligned)))  128 -> 64
  conv3x3_mma<2><<<dim3(1024, 1), 128, SMEM_BYTES>>>(p_ref16, p_al16, p_wr1,
                                                     b_r1, p_x1, nullptr, 64, 1);
  pack_act_kernel<<<dim3(64, 32, 2), 256>>>(p_x1, p_x116);
  // 4) out = relu(conv3x3(x1)) + aligned  64 -> 64
  conv3x3_mma<1><<<dim3(1024, 1), 128, SMEM_BYTES>>>(p_x116, nullptr, p_wr2,
                                                     b_r2, out, p_aligned, 64, 1);
}

// round 16
// speedup vs baseline: 1.7331x; 1.0651x over previous
#include <cuda_runtime.h>
#include <cuda_fp16.h>
#include <cstdint>

__device__ float g_doff[2 * 144 * 256 * 256];
__device__ float g_aligned[2 * 64 * 256 * 256];
__device__ float g_ref8[2 * 8 * 65536 * 8];  // channels-last ref per group
// packed fp16x2 activations: [b][pair(32)][HW]
__device__ uint32_t g_off16[2 * 32 * 65536];
__device__ uint32_t g_ref16[2 * 32 * 65536];
__device__ uint32_t g_al16[2 * 32 * 65536];
__device__ uint32_t g_x116[2 * 32 * 65536];
// packed fp16x2 weights (Ah layout): [oc][NHALF*288]
__device__ uint32_t g_wpk_off[144 * 288];
__device__ uint32_t g_wpk_r1[64 * 576];
__device__ uint32_t g_wpk_r2[64 * 288];

static constexpr int Hc = 256, Wc = 256, HWc = Hc * Wc;

static constexpr int BSTR = 136;
static constexpr int BST_U = 8 * 3 * BSTR;  // 3264 words per buffer
static constexpr int ASTR = 84;
static constexpr int AST_U = 64 * ASTR;     // 5376 words per buffer
static constexpr int SMEM_U = 2 * BST_U + 2 * AST_U;      // 17280
static constexpr size_t SMEM_BYTES = (size_t)SMEM_U * 4;  // 69120 B

__device__ __forceinline__ uint32_t packh2(float lo, float hi) {
  __half2 h = __floats2half2_rn(lo, hi);
  return *reinterpret_cast<uint32_t*>(&h);
}
__device__ __forceinline__ void mma16(float* c, uint32_t a0, uint32_t a1,
                                      uint32_t a2, uint32_t a3, uint32_t b0,
                                      uint32_t b1) {
  asm volatile(
      "mma.sync.aligned.m16n8k16.row.col.f32.f16.f16.f32 "
      "{%0,%1,%2,%3}, {%4,%5,%6,%7}, {%8,%9}, {%0,%1,%2,%3};"
      : "+f"(c[0]), "+f"(c[1]), "+f"(c[2]), "+f"(c[3])
      : "r"(a0), "r"(a1), "r"(a2), "r"(a3), "r"(b0), "r"(b1));
}
__device__ __forceinline__ void cp16(uint32_t dst, const void* src, int sz) {
  asm volatile("cp.async.cg.shared.global [%0], [%1], 16, %2;"
               :: "r"(dst), "l"(src), "r"(sz) : "memory");
}

// ---- prep: pack fp32 weights into fp16x2 Ah layout -------------------------
__global__ void pack_w_kernel(const float* __restrict__ w,
                              uint32_t* __restrict__ outp, int OC, int NHALF) {
  int idx = blockIdx.x * 256 + threadIdx.x;
  int KP = NHALF * 288;
  if (idx >= OC * KP) return;
  int oc = idx / KP, c = idx - oc * KP;
  int h = c / 288, r = c - h * 288;
  int chunk = r / 72, r2 = r - chunk * 72;
  int tap = r2 >> 3, p = r2 & 7;
  int Ktot = NHALF * 576;
  const float* wp = w + (size_t)oc * Ktot + (h * 64 + chunk * 16 + 2 * p) * 9 + tap;
  outp[idx] = packh2(wp[0], wp[9]);
}

// ---- prep: pack fp32 activations [b][64][HW] -> fp16x2 [b][32][HW] ---------
__global__ void pack_act_kernel(const float* __restrict__ in,
                                uint32_t* __restrict__ outp) {
  int i = blockIdx.x * 256 + threadIdx.x;
  int p = blockIdx.y, b = blockIdx.z;
  float4 v0 = *((const float4*)(in + ((size_t)(b * 64 + 2 * p)) * HWc) + i);
  float4 v1 = *((const float4*)(in + ((size_t)(b * 64 + 2 * p + 1)) * HWc) + i);
  uint4 u;
  u.x = packh2(v0.x, v1.x);
  u.y = packh2(v0.y, v1.y);
  u.z = packh2(v0.z, v1.z);
  u.w = packh2(v0.w, v1.w);
  *((uint4*)(outp + ((size_t)(b * 32 + p)) * HWc) + i) = u;
}

// ---- prep: ref -> channels-last per group: [b][g][HW][8] fp32 --------------
__global__ void pack_ref8_kernel(const float* __restrict__ in,
                                 float* __restrict__ outp) {
  int i = blockIdx.x * 256 + threadIdx.x;
  int g = blockIdx.y, b = blockIdx.z;
  float v[8];
#pragma unroll
  for (int c = 0; c < 8; c++)
    v[c] = in[((size_t)(b * 64 + g * 8 + c)) * HWc + i];
  float* dst = outp + (((size_t)(b * 8 + g)) * HWc + i) * 8;
  *(float4*)dst = *(float4*)v;
  *(float4*)(dst + 4) = *(float4*)(v + 4);
}

// CTA (128 thr, 4 warps): 128-px strip of row y x 64 output channels.
// 2-stage cp.async pipeline. If out16 != null, write packed fp16 only.
template <int NHALF>  // IC = NHALF*64
__global__ void __launch_bounds__(128, 3)
conv3x3_mma(const uint32_t* __restrict__ inA16, const uint32_t* __restrict__ inB16,
            const uint32_t* __restrict__ wpk, const float* __restrict__ bias,
            float* __restrict__ out, uint32_t* __restrict__ out16,
            const float* __restrict__ addsrc, int OC_total, int do_relu) {
  extern __shared__ uint32_t smu[];
  uint32_t* Bbuf[2] = {smu, smu + BST_U};
  uint32_t* Abuf[2] = {smu + 2 * BST_U, smu + 2 * BST_U + AST_U};
  const uint32_t smem_base = (uint32_t)__cvta_generic_to_shared(smu);
  const uint32_t Baddr[2] = {smem_base, smem_base + BST_U * 4};
  const uint32_t Aaddr[2] = {smem_base + 2 * BST_U * 4,
                             smem_base + (2 * BST_U + AST_U) * 4};

  const int t = threadIdx.x, lane = t & 31, wid = t >> 5;
  const int gid = lane >> 2, tig = lane & 3;
  const int wm = wid & 1, wn = wid >> 1;

  const int bx = blockIdx.x;
  const int xt = bx & 1, y = (bx >> 1) & 255, b = bx >> 9;
  const int x0 = xt * 128;
  const int oc0 = blockIdx.y * 64;
  const int OCv = min(64, OC_total - oc0);
  const int KPW = NHALF * 288;
  const int NC = NHALF * 4;

  const int rB = tig * (3 * BSTR) + wn * 64 + gid;

  float acc[2][8][4];
#pragma unroll
  for (int f = 0; f < 2; f++)
#pragma unroll
    for (int j = 0; j < 8; j++)
#pragma unroll
      for (int e = 0; e < 4; e++) acc[f][j][e] = 0.f;

  auto issue_chunk = [&](int cc, int buf) {
    const uint32_t* src = ((cc >> 2) == 0) ? inA16 : inB16;
    const int chunk = cc & 3;
    for (int i = t; i < 8 * 3 * 34; i += 128) {
      int p = i / 102, r = i - p * 102;
      int rr = r / 34, q = r - rr * 34;
      int gy = y + rr - 1;
      int gx0 = x0 + q * 4 - 4;
      bool ok = ((unsigned)gy < 256u) && gx0 >= 0 && gx0 <= 252;
      const uint32_t* sp = src + ((size_t)(b * 32 + chunk * 8 + p)) * HWc +
                           (size_t)(ok ? gy : 0) * 256 + (ok ? gx0 : 0);
      cp16(Baddr[buf] + ((p * 3 + rr) * BSTR + q * 4) * 4, sp, ok ? 16 : 0);
    }
    for (int i = t; i < 64 * 18; i += 128) {
      int m = i / 18, q4 = i - m * 18;
      bool ok = m < OCv;
      const uint32_t* sp = wpk + (size_t)(oc0 + (ok ? m : 0)) * KPW +
                           (cc >> 2) * 288 + chunk * 72 + q4 * 4;
      cp16(Aaddr[buf] + (m * ASTR + q4 * 4) * 4, sp, ok ? 16 : 0);
    }
    asm volatile("cp.async.commit_group;" ::: "memory");
  };

  issue_chunk(0, 0);

  for (int cc = 0; cc < NC; cc++) {
    __syncthreads();
    if (cc + 1 < NC) {
      issue_chunk(cc + 1, (cc + 1) & 1);
      asm volatile("cp.async.wait_group 1;" ::: "memory");
    } else {
      asm volatile("cp.async.wait_group 0;" ::: "memory");
    }
    __syncthreads();

    const uint32_t* Bst = Bbuf[cc & 1];
    const uint32_t* Ah = Abuf[cc & 1];
    if (wm * 32 < OCv) {
      const bool f1ok = (wm * 32 + 16) < OCv;
#pragma unroll
      for (int ks = 0; ks < 9; ks++) {
        const int ky = ks / 3, kx = ks % 3;
        const int rb0 = rB + ky * BSTR + kx + 3;
        const int rb1 = rb0 + 4 * 3 * BSTR;
        const int ar0 = (wm * 32 + gid) * ASTR + ks * 8 + tig;
        const int ar1 = ar0 + 16 * ASTR;
        uint32_t a00 = Ah[ar0], a01 = Ah[ar0 + 8 * ASTR];
        uint32_t a02 = Ah[ar0 + 4], a03 = Ah[ar0 + 8 * ASTR + 4];
        uint32_t a10 = f1ok ? Ah[ar1] : 0u;
        uint32_t a11 = f1ok ? Ah[ar1 + 8 * ASTR] : 0u;
        uint32_t a12 = f1ok ? Ah[ar1 + 4] : 0u;
        uint32_t a13 = f1ok ? Ah[ar1 + 8 * ASTR + 4] : 0u;
#pragma unroll
        for (int j = 0; j < 8; j++) {
          uint32_t b0 = Bst[rb0 + 8 * j];
          uint32_t b1 = Bst[rb1 + 8 * j];
          mma16(acc[0][j], a00, a01, a02, a03, b0, b1);
          if (f1ok) mma16(acc[1][j], a10, a11, a12, a13, b0, b1);
        }
      }
    }
  }

  // ---- epilogue ----
#pragma unroll
  for (int f = 0; f < 2; f++) {
#pragma unroll
    for (int half = 0; half < 2; half++) {
      int m = wm * 32 + f * 16 + gid + half * 8;
      if (m >= OCv) continue;
      int oc = oc0 + m;
      float bv = bias[oc];
      int px0 = x0 + wn * 64 + tig * 2;
      if (out16) {
        // packed fp16 output only (bit-identical to pack_act of fp32 result)
        __half* oh = (__half*)out16;
        size_t wbase = ((size_t)b * 32 + (oc >> 1)) * HWc + (size_t)y * 256 + px0;
        int par = oc & 1;
#pragma unroll
        for (int j = 0; j < 8; j++) {
          float v0 = acc[f][j][half * 2 + 0] + bv;
          float v1 = acc[f][j][half * 2 + 1] + bv;
          if (do_relu) { v0 = fmaxf(v0, 0.f); v1 = fmaxf(v1, 0.f); }
          oh[(wbase + j * 8) * 2 + par] = __float2half_rn(v0);
          oh[(wbase + j * 8 + 1) * 2 + par] = __float2half_rn(v1);
        }
      } else {
        size_t base = ((size_t)b * OC_total + oc) * HWc + (size_t)y * 256 + px0;
        float* op = out + base;
        const float* ap = addsrc ? addsrc + base : nullptr;
#pragma unroll
        for (int j = 0; j < 8; j++) {
          float v0 = acc[f][j][half * 2 + 0] + bv;
          float v1 = acc[f][j][half * 2 + 1] + bv;
          if (do_relu) { v0 = fmaxf(v0, 0.f); v1 = fmaxf(v1, 0.f); }
          if (ap) {
            float2 a2 = *(const float2*)(ap + j * 8);
            v0 += a2.x; v1 += a2.y;
          }
          *(float2*)(op + j * 8) = make_float2(v0, v1);
        }
      }
    }
  }
}

// ---------------- deformable conv (G=8, Cg=8, K=3), channels-last gather ----
__global__ __launch_bounds__(256) void deform_kernel(
    const float* __restrict__ ref8, const float* __restrict__ doff,
    const float* __restrict__ w_def, const float* __restrict__ b_def,
    float* __restrict__ outp, uint32_t* __restrict__ out16) {
  const int x = threadIdx.x, y = blockIdx.x, g = blockIdx.y, b = blockIdx.z;
  __shared__ float s_w[8][8][9];
  for (int i = threadIdx.x; i < 576; i += 256) {
    int o = i / 72, r = i - o * 72;
    s_w[o][0][r] = w_def[(g * 8 + o) * 72 + r];
  }
  __syncthreads();
  const float* r8 = ref8 + ((size_t)(b * 8 + g)) * HWc * 8;
  const float* offg = doff + (b * 144 + g * 18) * HWc + y * Wc + x;
  float acc[8];
#pragma unroll
  for (int o = 0; o < 8; o++) acc[o] = 0.f;
#pragma unroll 1
  for (int k = 0; k < 9; k++) {
    float dy = offg[(2 * k) * HWc];
    float dx = offg[(2 * k + 1) * HWc];
    float pyf = dy + (float)(y + k / 3 - 1);
    float pxf = dx + (float)(x + k % 3 - 1);
    float fy = floorf(pyf), fx = floorf(pxf);
    int y0 = (int)fy, x0 = (int)fx;
    float ly = pyf - fy, lx = pxf - fx;
    float w00 = (1.f - ly) * (1.f - lx), w01 = (1.f - ly) * lx;
    float w10 = ly * (1.f - lx), w11 = ly * lx;
    bool vy0 = (unsigned)y0 < 256u, vy1 = (unsigned)(y0 + 1) < 256u;
    bool vx0 = (unsigned)x0 < 256u, vx1 = (unsigned)(x0 + 1) < 256u;
    if (!(vy0 && vx0)) w00 = 0.f;
    if (!(vy0 && vx1)) w01 = 0.f;
    if (!(vy1 && vx0)) w10 = 0.f;
    if (!(vy1 && vx1)) w11 = 0.f;
    int cy0 = min(max(y0, 0), 255), cy1 = min(max(y0 + 1, 0), 255);
    int cx0 = min(max(x0, 0), 255), cx1 = min(max(x0 + 1, 0), 255);
    int i00 = cy0 * Wc + cx0, i01 = cy0 * Wc + cx1;
    int i10 = cy1 * Wc + cx0, i11 = cy1 * Wc + cx1;
    float v00[8], v01[8], v10[8], v11[8];
    *(float4*)v00 = *(const float4*)(r8 + (size_t)i00 * 8);
    *(float4*)(v00 + 4) = *(const float4*)(r8 + (size_t)i00 * 8 + 4);
    *(float4*)v01 = *(const float4*)(r8 + (size_t)i01 * 8);
    *(float4*)(v01 + 4) = *(const float4*)(r8 + (size_t)i01 * 8 + 4);
    *(float4*)v10 = *(const float4*)(r8 + (size_t)i10 * 8);
    *(float4*)(v10 + 4) = *(const float4*)(r8 + (size_t)i10 * 8 + 4);
    *(float4*)v11 = *(const float4*)(r8 + (size_t)i11 * 8);
    *(float4*)(v11 + 4) = *(const float4*)(r8 + (size_t)i11 * 8 + 4);
#pragma unroll
    for (int cch = 0; cch < 8; cch++) {
      float s = w00 * v00[cch] + w01 * v01[cch] + w10 * v10[cch] + w11 * v11[cch];
#pragma unroll
      for (int o = 0; o < 8; o++) acc[o] = fmaf(s, s_w[o][cch][k], acc[o]);
    }
  }
  float val[8];
#pragma unroll
  for (int o = 0; o < 8; o++) {
    val[o] = acc[o] + b_def[g * 8 + o];
    outp[(b * 64 + g * 8 + o) * HWc + y * Wc + x] = val[o];
  }
#pragma unroll
  for (int q = 0; q < 4; q++)
    out16[((size_t)(b * 32 + g * 4 + q)) * HWc + y * Wc + x] =
        packh2(val[2 * q], val[2 * q + 1]);
}

extern "C" void kernel_launch(void* const* d_in, const int* in_sizes, int n_in,
                              void* d_out, int out_size) {
  const float* offset = (const float*)d_in[0];
  const float* ref    = (const float*)d_in[1];
  const float* w_off  = (const float*)d_in[2];
  const float* b_off  = (const float*)d_in[3];
  const float* w_def  = (const float*)d_in[4];
  const float* b_def  = (const float*)d_in[5];
  const float* w_r1   = (const float*)d_in[6];
  const float* b_r1   = (const float*)d_in[7];
  const float* w_r2   = (const float*)d_in[8];
  const float* b_r2   = (const float*)d_in[9];
  float* out = (float*)d_out;

  float *p_doff, *p_aligned, *p_ref8;
  uint32_t *p_off16, *p_ref16, *p_al16, *p_x116;
  uint32_t *p_woff, *p_wr1, *p_wr2;
  cudaGetSymbolAddress((void**)&p_doff, g_doff);
  cudaGetSymbolAddress((void**)&p_aligned, g_aligned);
  cudaGetSymbolAddress((void**)&p_ref8, g_ref8);
  cudaGetSymbolAddress((void**)&p_off16, g_off16);
  cudaGetSymbolAddress((void**)&p_ref16, g_ref16);
  cudaGetSymbolAddress((void**)&p_al16, g_al16);
  cudaGetSymbolAddress((void**)&p_x116, g_x116);
  cudaGetSymbolAddress((void**)&p_woff, g_wpk_off);
  cudaGetSymbolAddress((void**)&p_wr1, g_wpk_r1);
  cudaGetSymbolAddress((void**)&p_wr2, g_wpk_r2);

  cudaFuncSetAttribute(conv3x3_mma<1>, cudaFuncAttributeMaxDynamicSharedMemorySize,
                       (int)SMEM_BYTES);
  cudaFuncSetAttribute(conv3x3_mma<2>, cudaFuncAttributeMaxDynamicSharedMemorySize,
                       (int)SMEM_BYTES);

  // prep
  pack_w_kernel<<<(144 * 288 + 255) / 256, 256>>>(w_off, p_woff, 144, 1);
  pack_w_kernel<<<(64 * 576 + 255) / 256, 256>>>(w_r1, p_wr1, 64, 2);
  pack_w_kernel<<<(64 * 288 + 255) / 256, 256>>>(w_r2, p_wr2, 64, 1);
  pack_act_kernel<<<dim3(64, 32, 2), 256>>>(offset, p_off16);
  pack_act_kernel<<<dim3(64, 32, 2), 256>>>(ref, p_ref16);
  pack_ref8_kernel<<<dim3(256, 8, 2), 256>>>(ref, p_ref8);

  // 1) deform_offsets = conv3x3(offset)  64 -> 144
  conv3x3_mma<1><<<dim3(1024, 3), 128, SMEM_BYTES>>>(
      p_off16, nullptr, p_woff, b_off, p_doff, nullptr, nullptr, 144, 0);
  // 2) deformable conv (writes fp32 aligned + packed al16)
  deform_kernel<<<dim3(256, 8, 2), 256>>>(p_ref8, p_doff, w_def, b_def,
                                          p_aligned, p_al16);
  // 3) x1 = relu(conv3x3(concat(ref, aligned)))  128 -> 64, packed output only
  conv3x3_mma<2><<<dim3(1024, 1), 128, SMEM_BYTES>>>(
      p_ref16, p_al16, p_wr1, b_r1, nullptr, p_x116, nullptr, 64, 1);
  // 4) out = relu(conv3x3(x1)) + aligned  64 -> 64
  conv3x3_mma<1><<<dim3(1024, 1), 128, SMEM_BYTES>>>(
      p_x116, nullptr, p_wr2, b_r2, out, nullptr, p_aligned, 64, 1);
}